// round 1
// baseline (speedup 1.0000x reference)
#include <cuda_runtime.h>
#include <math.h>

#define BB 16
#define NN 512
#define DD 64
#define JT 128
#define BN_EPS 1e-5f

// ---------------- scratch (static device globals; no runtime allocation) ----
__device__ float g_agg [BB * NN * DD];   // (B,N,64) attention-aggregated x
__device__ float g_xout[BB * NN * DD];   // pre-batchnorm output
__device__ float g_ps  [512 * 64];       // per-CTA partial sums   (stage 2)
__device__ float g_pq  [512 * 64];       // per-CTA partial sumsq  (stage 2)
__device__ float g_mean[64];
__device__ float g_istd[64];

__device__ __forceinline__ float tanh_fast(float x) {
    float y;
    asm("tanh.approx.f32 %0, %1;" : "=f"(y) : "f"(x));
    return y;
}

// ---------------------------------------------------------------------------
// Stage 1: per (b,i): A = W_att ⊙ x_i ; C = A @ X_b^T ; s_j = Σ_o v_o tanh(C+b);
//          softmax over j ; agg_i = Σ_j a_j x_j
// grid: (NN, BB) blocks, 256 threads. Dynamic smem.
// ---------------------------------------------------------------------------
__global__ void __launch_bounds__(256)
stage1_kernel(const float* __restrict__ x, const float* __restrict__ Wap,
              const float* __restrict__ bap, const float* __restrict__ attw)
{
    extern __shared__ float sm[];
    float* sA   = sm;              // 64*65   scaled weight rows (padded)
    float* sX   = sA + 64 * 65;    // 128*65  j-tile of x_b (padded)
    float* sxi  = sX + 128 * 65;   // 64
    float* sb   = sxi + 64;        // 64      att bias
    float* sv   = sb + 64;         // 64      att weight vector
    float* ss   = sv + 64;         // 512     scores -> exp weights
    float* sp   = ss + 512;        // 1024    partial buffers
    float* saux = sp + 1024;       // 32      cross-warp reductions

    const int t = threadIdx.x;
    const int lane = t & 31, wid = t >> 5;
    const int b = blockIdx.y, i = blockIdx.x;
    const float* __restrict__ xb = x + (size_t)b * NN * DD;

    if (t < 64) { sxi[t] = xb[i * DD + t]; sb[t] = bap[t]; sv[t] = attw[t]; }
    __syncthreads();
    for (int idx = t; idx < 64 * 64; idx += 256) {
        int o = idx >> 6, d = idx & 63;
        sA[o * 65 + d] = Wap[idx] * sxi[d];
    }
    __syncthreads();

    const int obase = wid * 8;                 // this warp's 8 output rows

    // ---------------- Pass A: scores for all 512 j ----------------
    for (int jt = 0; jt < 4; ++jt) {
        for (int idx = t; idx < JT * DD; idx += 256) {
            int j = idx >> 6, d = idx & 63;
            sX[j * 65 + d] = xb[(jt * JT + j) * DD + d];
        }
        __syncthreads();

        float acc[4][8];
        #pragma unroll
        for (int jj = 0; jj < 4; ++jj)
            #pragma unroll
            for (int oo = 0; oo < 8; ++oo) acc[jj][oo] = 0.0f;

        const float* Ar = sA + obase * 65;
        #pragma unroll 4
        for (int d = 0; d < 64; ++d) {
            float xv[4], av[8];
            #pragma unroll
            for (int jj = 0; jj < 4; ++jj) xv[jj] = sX[(lane + 32 * jj) * 65 + d];
            #pragma unroll
            for (int oo = 0; oo < 8; ++oo) av[oo] = Ar[oo * 65 + d];
            #pragma unroll
            for (int jj = 0; jj < 4; ++jj)
                #pragma unroll
                for (int oo = 0; oo < 8; ++oo)
                    acc[jj][oo] = fmaf(xv[jj], av[oo], acc[jj][oo]);
        }

        // tanh + weighted partial reduction over this warp's 8 o's
        #pragma unroll
        for (int jj = 0; jj < 4; ++jj) {
            float spart = 0.0f;
            #pragma unroll
            for (int oo = 0; oo < 8; ++oo) {
                float h = tanh_fast(acc[jj][oo] + sb[obase + oo]);
                spart = fmaf(h, sv[obase + oo], spart);
            }
            sp[wid * 128 + lane + 32 * jj] = spart;
        }
        __syncthreads();
        if (t < 128) {
            float s = 0.0f;
            #pragma unroll
            for (int g = 0; g < 8; ++g) s += sp[g * 128 + t];
            ss[jt * JT + t] = s;
        }
        __syncthreads();
    }

    // ---------------- softmax over j (512 values) ----------------
    float mym = fmaxf(ss[t], ss[t + 256]);
    #pragma unroll
    for (int o = 16; o; o >>= 1) mym = fmaxf(mym, __shfl_xor_sync(0xffffffffu, mym, o));
    if (lane == 0) saux[wid] = mym;
    __syncthreads();
    float M = saux[0];
    #pragma unroll
    for (int w = 1; w < 8; ++w) M = fmaxf(M, saux[w]);
    __syncthreads();

    float e0 = __expf(ss[t] - M);
    float e1 = __expf(ss[t + 256] - M);
    ss[t] = e0; ss[t + 256] = e1;
    float sum = e0 + e1;
    #pragma unroll
    for (int o = 16; o; o >>= 1) sum += __shfl_xor_sync(0xffffffffu, sum, o);
    if (lane == 0) saux[wid] = sum;
    __syncthreads();
    float tot = 0.0f;
    #pragma unroll
    for (int w = 0; w < 8; ++w) tot += saux[w];
    const float inv = 1.0f / tot;

    // ---------------- Pass B: agg = (Σ_j e_j x_j) * inv ----------------
    const int d = t & 63, jg = t >> 6;
    float ag = 0.0f;
    for (int jt = 0; jt < 4; ++jt) {
        __syncthreads();
        for (int idx = t; idx < JT * DD; idx += 256) {
            int j = idx >> 6, dd2 = idx & 63;
            sX[j * 65 + dd2] = xb[(jt * JT + j) * DD + dd2];
        }
        __syncthreads();
        const float* as = ss + jt * JT + jg * 32;
        #pragma unroll 8
        for (int jl = 0; jl < 32; ++jl)
            ag = fmaf(as[jl], sX[(jg * 32 + jl) * 65 + d], ag);
    }
    __syncthreads();
    sp[jg * 64 + d] = ag;
    __syncthreads();
    if (t < 64) {
        float a = (sp[t] + sp[64 + t] + sp[128 + t] + sp[192 + t]) * inv;
        g_agg[((size_t)b * NN + i) * DD + t] = a;
    }
}

// ---------------------------------------------------------------------------
// Stage 2: x_out = agg@W_with^T + x@W_without^T + biases ; per-CTA BN partials
// grid: 512 blocks × 256 threads, 16 rows per block.
// ---------------------------------------------------------------------------
__global__ void __launch_bounds__(256)
stage2_kernel(const float* __restrict__ x,
              const float* __restrict__ Wwith, const float* __restrict__ bwith,
              const float* __restrict__ Wwo,   const float* __restrict__ bwo)
{
    __shared__ float sWw[64 * 65], sWo[64 * 65];
    __shared__ float sag[16 * 64], sx[16 * 64];
    __shared__ float rs[4 * 64], rq[4 * 64];

    const int t = threadIdx.x;
    const int r0 = blockIdx.x * 16;

    for (int idx = t; idx < 64 * 64; idx += 256) {
        int o = idx >> 6, d = idx & 63;
        sWw[o * 65 + d] = Wwith[idx];
        sWo[o * 65 + d] = Wwo[idx];
    }
    for (int idx = t; idx < 16 * 64; idx += 256) {
        sag[idx] = g_agg[(size_t)r0 * 64 + idx];
        sx[idx]  = x    [(size_t)r0 * 64 + idx];
    }
    __syncthreads();

    const int o = t & 63, rg = t >> 6;
    const float bias = bwith[o] + bwo[o];
    float lsum = 0.0f, lsq = 0.0f;
    #pragma unroll
    for (int rr = 0; rr < 4; ++rr) {
        const int r = rg + rr * 4;
        float acc = bias;
        #pragma unroll 8
        for (int d = 0; d < 64; ++d)
            acc += sag[r * 64 + d] * sWw[o * 65 + d]
                 + sx [r * 64 + d] * sWo[o * 65 + d];
        g_xout[(size_t)(r0 + r) * 64 + o] = acc;
        lsum += acc;
        lsq  = fmaf(acc, acc, lsq);
    }
    rs[rg * 64 + o] = lsum;
    rq[rg * 64 + o] = lsq;
    __syncthreads();
    if (t < 64) {
        float s = rs[t] + rs[64 + t] + rs[128 + t] + rs[192 + t];
        float q = rq[t] + rq[64 + t] + rq[128 + t] + rq[192 + t];
        g_ps[blockIdx.x * 64 + t] = s;
        g_pq[blockIdx.x * 64 + t] = q;
    }
}

// ---------------------------------------------------------------------------
// Stage 3a: reduce partials -> mean / inv-std (deterministic, no atomics)
// ---------------------------------------------------------------------------
__global__ void stage3a_kernel()
{
    const int o = threadIdx.x;   // 64 threads
    float s = 0.0f, q = 0.0f;
    for (int c = 0; c < 512; ++c) {
        s += g_ps[c * 64 + o];
        q += g_pq[c * 64 + o];
    }
    const float mean = s * (1.0f / 8192.0f);
    const float var  = q * (1.0f / 8192.0f) - mean * mean;
    g_mean[o] = mean;
    g_istd[o] = rsqrtf(var + BN_EPS);
}

// ---------------------------------------------------------------------------
// Stage 3b: batchnorm affine + SELU, write output
// ---------------------------------------------------------------------------
__global__ void __launch_bounds__(512)
stage3b_kernel(const float* __restrict__ gamma, const float* __restrict__ beta,
               float* __restrict__ out)
{
    const int idx = blockIdx.x * 512 + threadIdx.x;
    const int o = idx & 63;
    float v = g_xout[idx];
    float n = (v - g_mean[o]) * g_istd[o] * gamma[o] + beta[o];
    const float alpha = 1.6732632423543772f;
    const float lam   = 1.0507009873554805f;
    out[idx] = (n > 0.0f) ? lam * n : lam * alpha * expm1f(n);
}

// ---------------------------------------------------------------------------
extern "C" void kernel_launch(void* const* d_in, const int* in_sizes, int n_in,
                              void* d_out, int out_size)
{
    const float* x     = (const float*)d_in[0];
    const float* Wap   = (const float*)d_in[1];
    const float* bap   = (const float*)d_in[2];
    const float* attw  = (const float*)d_in[3];
    const float* Wwith = (const float*)d_in[4];
    const float* bwith = (const float*)d_in[5];
    const float* Wwo   = (const float*)d_in[6];
    const float* bwo   = (const float*)d_in[7];
    const float* gamma = (const float*)d_in[8];
    const float* beta  = (const float*)d_in[9];
    float* out = (float*)d_out;

    const int smem1 = (64 * 65 + 128 * 65 + 64 * 3 + 512 + 1024 + 32) * 4; // 56992 B
    cudaFuncSetAttribute(stage1_kernel,
                         cudaFuncAttributeMaxDynamicSharedMemorySize, smem1);

    dim3 g1(NN, BB);
    stage1_kernel<<<g1, 256, smem1>>>(x, Wap, bap, attw);
    stage2_kernel<<<512, 256>>>(x, Wwith, bwith, Wwo, bwo);
    stage3a_kernel<<<1, 64>>>();
    stage3b_kernel<<<(BB * NN * DD) / 512, 512>>>(gamma, beta, out);
}